// round 10
// baseline (speedup 1.0000x reference)
#include <cuda_runtime.h>
#include <cuda_fp16.h>
#include <cstdint>

// ============================================================================
// GaussianMLP fused — sm_103 plain target, fp16 mma.sync.m16n8k16.
// R10: 1024 thr (32 warps), warp tile M32xN32 (4Mx8N), K=64 mega-stages
//      (6 stages, 3-slot swizzled cp.async ring), precomputed swizzle offsets.
// ============================================================================

#define NTILES 4096

__device__ __forceinline__ uint32_t smem_u32(const void* p) {
    uint32_t a;
    asm("{ .reg .u64 t; cvta.to.shared.u64 t, %1; cvt.u32.u64 %0, t; }" : "=r"(a) : "l"(p));
    return a;
}
__device__ __forceinline__ void mma16(float* c, const uint32_t* a, uint32_t b0, uint32_t b1) {
    asm volatile(
        "mma.sync.aligned.m16n8k16.row.col.f32.f16.f16.f32 "
        "{%0,%1,%2,%3},{%4,%5,%6,%7},{%8,%9},{%0,%1,%2,%3};"
        : "+f"(c[0]), "+f"(c[1]), "+f"(c[2]), "+f"(c[3])
        : "r"(a[0]), "r"(a[1]), "r"(a[2]), "r"(a[3]), "r"(b0), "r"(b1));
}
__device__ __forceinline__ void ldsm4(uint32_t* r, uint32_t addr) {
    asm volatile("ldmatrix.sync.aligned.m8n8.x4.shared.b16 {%0,%1,%2,%3}, [%4];"
                 : "=r"(r[0]), "=r"(r[1]), "=r"(r[2]), "=r"(r[3]) : "r"(addr));
}
#define CP16CG(dst, src) \
    asm volatile("cp.async.cg.shared.global [%0], [%1], 16;" :: "r"(dst), "l"(src))
#define CP_COMMIT() asm volatile("cp.async.commit_group;" ::: "memory")
#define CP_WAIT1()  asm volatile("cp.async.wait_group 1;" ::: "memory")
#define CP_WAIT0()  asm volatile("cp.async.wait_group 0;" ::: "memory")

// ---------------- pre-converted half weights, [n][k] -------------------------
__device__ __align__(16) __half g_wemb_h[256 * 128];
__device__ __align__(16) __half g_w2_h[256 * 256];    // n<128: Wm, else Wl

__global__ void prep_kernel(const float* __restrict__ We,
                            const float* __restrict__ Wm,
                            const float* __restrict__ Wl) {
    int i = blockIdx.x * 256 + threadIdx.x;
    if (i < 32768) {
        int n = i >> 7, k = i & 127;
        g_wemb_h[i] = __float2half(We[k * 256 + n]);
    } else if (i < 98304) {
        int j = i - 32768;
        int n = j >> 8, k = j & 255;
        float v = (n < 128) ? Wm[k * 128 + n] : Wl[k * 128 + (n - 128)];
        g_w2_h[j] = __float2half(v);
    }
}

// ---------------- SMEM map (217088 B) ----------------------------------------
// hs   : h half tile [128][264] (528B rows, padded)      67584
// ring : 3 x 49152  (W [256]x128B swizzled @+0, x [128]x128B swizzled @+32768)
// bias : 2048
#define HS_OFF    0u
#define RING_OFF  67584u
#define SLOT_SZ   49152u
#define XOFF_X    32768u
#define SBE_OFF   215040u
#define SBM_OFF   216064u
#define SBL_OFF   216576u
#define SMEM_TOTAL 217088
#define HS_SB 528u        // hs row stride BYTES
#define MS_S 132          // floats (epilogue logvar exchange)

__global__ void __launch_bounds__(1024, 1)
gauss_kernel(const float* __restrict__ x, const float* __restrict__ eps,
             const float* __restrict__ be, const float* __restrict__ bm,
             const float* __restrict__ bl, float* __restrict__ out) {
    extern __shared__ char smem[];
    const uint32_t sm = smem_u32(smem);
    float* sbe = (float*)(smem + SBE_OFF);
    float* sbm = (float*)(smem + SBM_OFF);
    float* sbl = (float*)(smem + SBL_OFF);

    const int tid  = threadIdx.x;
    const int wid  = tid >> 5, lane = tid & 31;
    const int g    = lane >> 2, tg = lane & 3;
    const int mw   = wid & 3;                 // M block (32 rows): 4
    const int nw   = wid >> 2;                // N block (32 cols): 8
    const int nb   = nw * 32;
    const size_t tile = blockIdx.x;

    const int fr_row = lane & 15;
    const uint32_t fr_kb = (lane & 16) ? 16u : 0u;
    const uint32_t S = ((uint32_t)(lane & 7)) << 4;
    uint32_t xoff[4];
    #pragma unroll
    for (int kk = 0; kk < 4; kk++) xoff[kk] = (((uint32_t)(kk * 32)) | fr_kb) ^ S;

    if (tid < 256) sbe[tid] = be[tid];
    if (tid < 128) { sbm[tid] = bm[tid]; sbl[tid] = bl[tid]; }

    const float* xg = x + tile * 16384;

    // ring helpers ------------------------------------------------------------
    auto slotb = [&](int i) -> uint32_t {
        return sm + RING_OFF + (uint32_t)(i % 3) * SLOT_SZ;
    };
    // W chunk [256 rows][64 k-halves], swizzled 128B rows
    auto issue_stage = [&](int i) {
        if (i >= 6) return;
        uint32_t base = slotb(i);
        const __half* w = (i < 2) ? (g_wemb_h + i * 64) : (g_w2_h + (i - 2) * 64);
        const int rs = (i < 2) ? 128 : 256;
        const int row = tid >> 2, seg = tid & 3;
        const uint32_t rsw = ((uint32_t)(row & 7)) << 4;
        CP16CG(base + (uint32_t)(row * 128) + (((uint32_t)(seg * 16)) ^ rsw),
               w + row * rs + seg * 8);
        CP16CG(base + (uint32_t)(row * 128) + (((uint32_t)(seg * 16 + 64)) ^ rsw),
               w + row * rs + seg * 8 + 32);
        CP_COMMIT();
    };
    // x chunk: LDG fp32 -> cvt -> STS swizzled
    const int x_row = tid >> 3, x_q = tid & 7;
    float4 xr0, xr1;
    auto ldg_x = [&](int s) {
        const float* p = xg + x_row * 128 + s * 64 + x_q * 8;
        xr0 = *(const float4*)p;
        xr1 = *(const float4*)(p + 4);
    };
    auto sts_x = [&](int s) {
        __half2 h0 = __floats2half2_rn(xr0.x, xr0.y);
        __half2 h1 = __floats2half2_rn(xr0.z, xr0.w);
        __half2 h2 = __floats2half2_rn(xr1.x, xr1.y);
        __half2 h3 = __floats2half2_rn(xr1.z, xr1.w);
        uint4 u;
        u.x = *(uint32_t*)&h0; u.y = *(uint32_t*)&h1;
        u.z = *(uint32_t*)&h2; u.w = *(uint32_t*)&h3;
        uint32_t a = slotb(s) + XOFF_X + (uint32_t)(x_row * 128)
                   + (((uint32_t)(x_q * 16)) ^ (((uint32_t)(x_row & 7)) << 4));
        *(uint4*)(smem + (a - sm)) = u;
    };

    float acc[2][4][4];
    #pragma unroll
    for (int m = 0; m < 2; m++)
        #pragma unroll
        for (int q = 0; q < 4; q++)
            #pragma unroll
            for (int c = 0; c < 4; c++) acc[m][q][c] = 0.0f;

    // prologue
    issue_stage(0);
    issue_stage(1);
    ldg_x(0); sts_x(0);
    ldg_x(1);

    // ======================= layer 1 (stages 0..1, K=64) =====================
    #pragma unroll 1
    for (int s = 0; s < 2; s++) {
        CP_WAIT1();
        __syncthreads();
        issue_stage(s + 2);
        if (s == 0) sts_x(1);

        const uint32_t sb = slotb(s);
        const uint32_t aR = sb + XOFF_X + (uint32_t)((mw * 32 + fr_row) * 128);
        const uint32_t bR = sb + (uint32_t)((nb + fr_row) * 128);
        #pragma unroll
        for (int kk = 0; kk < 4; kk++) {
            uint32_t A0[4], A1[4], B0[4], B1[4];
            ldsm4(A0, aR + xoff[kk]);
            ldsm4(A1, aR + 2048u + xoff[kk]);
            ldsm4(B0, bR + xoff[kk]);
            ldsm4(B1, bR + 2048u + xoff[kk]);
            mma16(acc[0][0], A0, B0[0], B0[2]);
            mma16(acc[0][1], A0, B0[1], B0[3]);
            mma16(acc[0][2], A0, B1[0], B1[2]);
            mma16(acc[0][3], A0, B1[1], B1[3]);
            mma16(acc[1][0], A1, B0[0], B0[2]);
            mma16(acc[1][1], A1, B0[1], B0[3]);
            mma16(acc[1][2], A1, B1[0], B1[2]);
            mma16(acc[1][3], A1, B1[1], B1[3]);
        }
    }

    // ---- h = half(relu(acc + b_emb)) -> hs (padded rows, no swizzle) --------
    {
        #pragma unroll
        for (int m = 0; m < 2; m++) {
            const int r0 = mw * 32 + m * 16 + g;
            #pragma unroll
            for (int q = 0; q < 4; q++) {
                int col = nb + q * 8 + 2 * tg;
                float b0v = sbe[col], b1v = sbe[col + 1];
                __half2 v0 = __floats2half2_rn(fmaxf(acc[m][q][0] + b0v, 0.0f),
                                               fmaxf(acc[m][q][1] + b1v, 0.0f));
                __half2 v1 = __floats2half2_rn(fmaxf(acc[m][q][2] + b0v, 0.0f),
                                               fmaxf(acc[m][q][3] + b1v, 0.0f));
                *(__half2*)(smem + HS_OFF + (uint32_t)r0 * HS_SB + (uint32_t)(col * 2))       = v0;
                *(__half2*)(smem + HS_OFF + (uint32_t)(r0 + 8) * HS_SB + (uint32_t)(col * 2)) = v1;
            }
        }
    }
    #pragma unroll
    for (int m = 0; m < 2; m++)
        #pragma unroll
        for (int q = 0; q < 4; q++)
            #pragma unroll
            for (int c = 0; c < 4; c++) acc[m][q][c] = 0.0f;

    // ======================= layer 2 (stages 2..5, K=64) =====================
    #pragma unroll 1
    for (int s = 2; s < 6; s++) {
        if (s == 5) { CP_WAIT0(); } else { CP_WAIT1(); }
        __syncthreads();                 // stage-s W visible; (s==2) h visible
        issue_stage(s + 2);

        const uint32_t aH = sm + HS_OFF + (uint32_t)((mw * 32 + fr_row)) * HS_SB
                          + (uint32_t)((s - 2) * 128) + fr_kb;
        const uint32_t bR = slotb(s) + (uint32_t)((nb + fr_row) * 128);
        #pragma unroll
        for (int kk = 0; kk < 4; kk++) {
            uint32_t A0[4], A1[4], B0[4], B1[4];
            ldsm4(A0, aH + (uint32_t)(kk * 32));
            ldsm4(A1, aH + 16u * HS_SB + (uint32_t)(kk * 32));
            ldsm4(B0, bR + xoff[kk]);
            ldsm4(B1, bR + 2048u + xoff[kk]);
            mma16(acc[0][0], A0, B0[0], B0[2]);
            mma16(acc[0][1], A0, B0[1], B0[3]);
            mma16(acc[0][2], A0, B1[0], B1[2]);
            mma16(acc[0][3], A0, B1[1], B1[3]);
            mma16(acc[1][0], A1, B0[0], B0[2]);
            mma16(acc[1][1], A1, B0[1], B0[3]);
            mma16(acc[1][2], A1, B1[0], B1[2]);
            mma16(acc[1][3], A1, B1[1], B1[3]);
        }
    }
    __syncthreads();   // hs reads complete — reuse base region for logvar tile

    // ============== epilogue: register-direct, fragment layout ===============
    if (nw >= 4) {     // logvar warps (cols 128..255)
        float* ls = (float*)smem;
        const int cb2 = nb - 128;
        float* olg = out + 134217728u + tile * 16384;
        #pragma unroll
        for (int m = 0; m < 2; m++) {
            const int rA = mw * 32 + m * 16 + g, rB = rA + 8;
            #pragma unroll
            for (int q = 0; q < 4; q++) {
                int cc = cb2 + q * 8 + 2 * tg;
                float b0v = sbl[cc], b1v = sbl[cc + 1];
                float2 v0 = make_float2(acc[m][q][0] + b0v, acc[m][q][1] + b1v);
                float2 v1 = make_float2(acc[m][q][2] + b0v, acc[m][q][3] + b1v);
                *(float2*)&ls[rA * MS_S + cc] = v0;
                *(float2*)&ls[rB * MS_S + cc] = v1;
                *(float2*)&olg[rA * 128 + cc] = v0;
                *(float2*)&olg[rB * 128 + cc] = v1;
            }
        }
    }
    __syncthreads();
    if (nw < 4) {      // mean warps (cols 0..127)
        const float* ls = (const float*)smem;
        const float* eg = eps + tile * 16384;
        float* oz = out + tile * 16384;
        float* om = out + 67108864u + tile * 16384;
        #pragma unroll
        for (int m = 0; m < 2; m++) {
            const int rA = mw * 32 + m * 16 + g, rB = rA + 8;
            #pragma unroll
            for (int q = 0; q < 4; q++) {
                int cc = nb + q * 8 + 2 * tg;
                float b0v = sbm[cc], b1v = sbm[cc + 1];
                float2 m0 = make_float2(acc[m][q][0] + b0v, acc[m][q][1] + b1v);
                float2 m1 = make_float2(acc[m][q][2] + b0v, acc[m][q][3] + b1v);
                float2 l0 = *(const float2*)&ls[rA * MS_S + cc];
                float2 l1 = *(const float2*)&ls[rB * MS_S + cc];
                float2 e0 = *(const float2*)&eg[rA * 128 + cc];
                float2 e1 = *(const float2*)&eg[rB * 128 + cc];
                float2 z0, z1;
                z0.x = fmaf(__expf(0.5f * l0.x), e0.x, m0.x);
                z0.y = fmaf(__expf(0.5f * l0.y), e0.y, m0.y);
                z1.x = fmaf(__expf(0.5f * l1.x), e1.x, m1.x);
                z1.y = fmaf(__expf(0.5f * l1.y), e1.y, m1.y);
                *(float2*)&oz[rA * 128 + cc] = z0;
                *(float2*)&oz[rB * 128 + cc] = z1;
                *(float2*)&om[rA * 128 + cc] = m0;
                *(float2*)&om[rB * 128 + cc] = m1;
            }
        }
    }
}

// ---------------------------------------------------------------------------

extern "C" void kernel_launch(void* const* d_in, const int* in_sizes, int n_in,
                              void* d_out, int out_size) {
    const float* x   = (const float*)d_in[0];
    const float* eps = (const float*)d_in[1];
    const float* We  = (const float*)d_in[2];
    const float* be  = (const float*)d_in[3];
    const float* Wm  = (const float*)d_in[4];
    const float* bm  = (const float*)d_in[5];
    const float* Wl  = (const float*)d_in[6];
    const float* bl  = (const float*)d_in[7];
    float* out = (float*)d_out;

    cudaFuncSetAttribute(gauss_kernel, cudaFuncAttributeMaxDynamicSharedMemorySize, SMEM_TOTAL);
    prep_kernel<<<384, 256>>>(We, Wm, Wl);
    gauss_kernel<<<NTILES, 1024, SMEM_TOTAL>>>(x, eps, be, bm, bl, out);
}